// round 5
// baseline (speedup 1.0000x reference)
#include <cuda_runtime.h>
#include <math.h>

// Problem constants
#define BATCH  512
#define INDIM  256
#define CONDD  128
#define NEXP   8
#define HD     64
#define DP     64
#define DN     128
#define TPE    49280      // INDIM*DP + INDIM*DN + DN
#define TOTALW 394240     // NEXP*TPE
#define NCOL   1536       // NEXP*(DP+DN)

// GEMM K layout:
//  [0,16384)      : A = h[b,hh]*x[b,i]  (k = hh*256 + i)  <-> B = hW2 wp/wn slices
//  [16384,16640)  : A = x[b,i]                            <-> B = base_wp/base_wn + hb2 wp/wn
//  [16640,16704)  : A = h[b,hh]                           <-> B = hW2 bn slice (wn cols only)
//  16704          : A = 1.0                               <-> B = base_bn + hb2 bn (wn cols only)
//  [16705,16736)  : zero pad
#define KP       16736
#define KT_TILES 523      // KP / 32

#define BM 64
#define BN 64
#define BK 32

// ---------------- scratch (no allocation allowed) ----------------
__device__ float g_h[BATCH * HD];
__device__ float g_gw[BATCH * NEXP];
__device__ float g_At[KP * BATCH];          // A transposed [k][b], tf32-rounded, 34.3 MB
__device__ float g_pre[2 * BATCH * NCOL];   // split-K partials

__device__ __forceinline__ float tf32r(float x) {
    float y;
    asm("cvt.rna.tf32.f32 %0, %1;" : "=f"(y) : "f"(x));
    return y;
}

__device__ __forceinline__ float4 ld4(const float* p) {
    return *reinterpret_cast<const float4*>(p);
}

// ---------------- kernel 1: cond head (h + gates) ----------------
__global__ void head_kernel(const float* __restrict__ cond,
                            const float* __restrict__ hW1, const float* __restrict__ hb1,
                            const float* __restrict__ gW1, const float* __restrict__ gb1,
                            const float* __restrict__ gW2, const float* __restrict__ gb2) {
    int b = blockIdx.x;
    int tid = threadIdx.x;
    __shared__ float cs[CONDD];
    __shared__ float ts[24];
    __shared__ float lg[NEXP];

    cs[tid] = cond[b * CONDD + tid];
    __syncthreads();

    if (tid < HD) {
        float acc = hb1[tid];
#pragma unroll 8
        for (int i = 0; i < CONDD; i++) acc += cs[i] * hW1[i * HD + tid];
        g_h[b * HD + tid] = fmaxf(acc, 0.f);
    } else if (tid < HD + 24) {
        int j = tid - HD;
        float acc = gb1[j];
#pragma unroll 8
        for (int i = 0; i < CONDD; i++) acc += cs[i] * gW1[i * 24 + j];
        ts[j] = fmaxf(acc, 0.f);
    }
    __syncthreads();

    if (tid < NEXP) {
        float acc = gb2[tid];
#pragma unroll
        for (int t = 0; t < 24; t++) acc += ts[t] * gW2[t * NEXP + tid];
        lg[tid] = acc;
    }
    __syncthreads();

    if (tid == 0) {
        float mx = lg[0];
#pragma unroll
        for (int e = 1; e < NEXP; e++) mx = fmaxf(mx, lg[e]);
        float ex[NEXP];
        float s = 0.f;
#pragma unroll
        for (int e = 0; e < NEXP; e++) { ex[e] = expf(lg[e] - mx); s += ex[e]; }
        float inv = 1.f / s;
#pragma unroll
        for (int e = 0; e < NEXP; e++) g_gw[b * NEXP + e] = ex[e] * inv;
    }
}

// ---------------- kernel 2: pack A^T [KP][BATCH], tf32-rounded ----------------
__global__ void packA_kernel(const float* __restrict__ x) {
    int idx = blockIdx.x * blockDim.x + threadIdx.x;   // one float4 over b
    int k = idx >> 7;              // / 128 (=512/4 float4 per k-row)
    int b0 = (idx & 127) << 2;     // * 4
    float v[4];
    if (k < 16384) {
        int hh = k >> 8, i = k & 255;
#pragma unroll
        for (int r = 0; r < 4; r++)
            v[r] = g_h[(b0 + r) * HD + hh] * x[(b0 + r) * INDIM + i];
    } else if (k < 16640) {
        int i = k - 16384;
#pragma unroll
        for (int r = 0; r < 4; r++) v[r] = x[(b0 + r) * INDIM + i];
    } else if (k < 16704) {
        int hh = k - 16640;
#pragma unroll
        for (int r = 0; r < 4; r++) v[r] = g_h[(b0 + r) * HD + hh];
    } else if (k == 16704) {
#pragma unroll
        for (int r = 0; r < 4; r++) v[r] = 1.0f;
    } else {
#pragma unroll
        for (int r = 0; r < 4; r++) v[r] = 0.0f;
    }
    float4 o;
    o.x = tf32r(v[0]); o.y = tf32r(v[1]); o.z = tf32r(v[2]); o.w = tf32r(v[3]);
    *reinterpret_cast<float4*>(&g_At[k * BATCH + b0]) = o;
}

// ---------------- B gather: row (k), 4 contiguous cols starting at c ----------------
// Column group: nt = n*3 + r; r==0 -> wp j=c, r==1 -> wn q=c, r==2 -> wn q=64+c
__device__ __forceinline__ float4 loadB(int k, int c, int n, int r,
                                        const float* __restrict__ hW2,
                                        const float* __restrict__ hb2,
                                        const float* __restrict__ base_wp,
                                        const float* __restrict__ base_wn,
                                        const float* __restrict__ base_bn) {
    float4 z = make_float4(0.f, 0.f, 0.f, 0.f);
    if (k < 16384) {
        int hh = k >> 8, i = k & 255;
        int off = hh * TOTALW + n * TPE;
        if (r == 0) return ld4(hW2 + off + i * DP + c);
        return ld4(hW2 + off + INDIM * DP + i * DN + (r - 1) * 64 + c);
    }
    if (k < 16640) {
        int i = k - 16384;
        if (r == 0) {
            float4 a = ld4(base_wp + (n * INDIM + i) * DP + c);
            float4 h = ld4(hb2 + n * TPE + i * DP + c);
            return make_float4(a.x + h.x, a.y + h.y, a.z + h.z, a.w + h.w);
        }
        int j = (r - 1) * 64 + c;
        float4 a = ld4(base_wn + (n * INDIM + i) * DN + j);
        float4 h = ld4(hb2 + n * TPE + INDIM * DP + i * DN + j);
        return make_float4(a.x + h.x, a.y + h.y, a.z + h.z, a.w + h.w);
    }
    if (k < 16704) {
        if (r == 0) return z;
        int hh = k - 16640;
        return ld4(hW2 + hh * TOTALW + n * TPE + INDIM * (DP + DN) + (r - 1) * 64 + c);
    }
    if (k == 16704) {
        if (r == 0) return z;
        int j = (r - 1) * 64 + c;
        float4 a = ld4(base_bn + n * DN + j);
        float4 h = ld4(hb2 + n * TPE + INDIM * (DP + DN) + j);
        return make_float4(a.x + h.x, a.y + h.y, a.z + h.z, a.w + h.w);
    }
    return z;
}

// m16n8k8 tf32 warp MMA (fallback HMMA path on sm_103a)
__device__ __forceinline__ void mma_tf32(float* d, const float* a, const float* b) {
    const unsigned* A = reinterpret_cast<const unsigned*>(a);
    const unsigned* Bv = reinterpret_cast<const unsigned*>(b);
    asm volatile(
        "mma.sync.aligned.m16n8k8.row.col.f32.tf32.tf32.f32 "
        "{%0,%1,%2,%3}, {%4,%5,%6,%7}, {%8,%9}, {%0,%1,%2,%3};\n"
        : "+f"(d[0]), "+f"(d[1]), "+f"(d[2]), "+f"(d[3])
        : "r"(A[0]), "r"(A[1]), "r"(A[2]), "r"(A[3]), "r"(Bv[0]), "r"(Bv[1]));
}

// ---------------- kernel 3: GEMM pre[b, n*192+j] with split-K=2 ----------------
__global__ void __launch_bounds__(128) gemm_kernel(
    const float* __restrict__ hW2, const float* __restrict__ hb2,
    const float* __restrict__ base_wp, const float* __restrict__ base_wn,
    const float* __restrict__ base_bn) {

    __shared__ __align__(16) float As[2][BK][BM + 8];
    __shared__ __align__(16) float Bs[2][BK][BN + 8];

    const int tid  = threadIdx.x;
    const int lane = tid & 31;
    const int g    = lane >> 2;
    const int t    = lane & 3;
    const int warp = tid >> 5;
    const int mw   = (warp >> 1) * 32;   // warp tile 32x32, 2x2 warps
    const int nw   = (warp & 1) * 32;

    const int nt = blockIdx.x;    // 0..23
    const int mt = blockIdx.y;    // 0..7
    const int kspl = blockIdx.z;  // 0..1
    const int n = nt / 3, r = nt % 3;
    const int kt0 = (kspl == 0) ? 0 : 262;
    const int kt1 = (kspl == 0) ? 262 : KT_TILES;

    const int rb = tid >> 4;            // smem row base 0..7
    const int cb = (tid & 15) * 4;      // smem col 0..60

    float acc[2][4][4];
#pragma unroll
    for (int mi = 0; mi < 2; mi++)
#pragma unroll
        for (int ni = 0; ni < 4; ni++)
#pragma unroll
            for (int q = 0; q < 4; q++) acc[mi][ni][q] = 0.f;

    float4 stA[4], stB[4];

    // prologue: stage tile kt0
    {
        int kbase = kt0 * BK;
#pragma unroll
        for (int it = 0; it < 4; it++) {
            int kk = rb + it * 8;
            stA[it] = ld4(&g_At[(kbase + kk) * BATCH + mt * BM + cb]);
            stB[it] = loadB(kbase + kk, cb, n, r, hW2, hb2, base_wp, base_wn, base_bn);
        }
    }

    int p = 0;
    for (int kt = kt0; kt < kt1; kt++) {
        // commit staged tile into smem[p]
#pragma unroll
        for (int it = 0; it < 4; it++) {
            int kk = rb + it * 8;
            *reinterpret_cast<float4*>(&As[p][kk][cb]) = stA[it];
            float4 bv = stB[it];
            bv.x = tf32r(bv.x); bv.y = tf32r(bv.y);
            bv.z = tf32r(bv.z); bv.w = tf32r(bv.w);
            *reinterpret_cast<float4*>(&Bs[p][kk][cb]) = bv;
        }
        __syncthreads();

        // stage next tile (gmem loads overlap with MMA below)
        if (kt + 1 < kt1) {
            int kbase = (kt + 1) * BK;
#pragma unroll
            for (int it = 0; it < 4; it++) {
                int kk = rb + it * 8;
                stA[it] = ld4(&g_At[(kbase + kk) * BATCH + mt * BM + cb]);
                stB[it] = loadB(kbase + kk, cb, n, r, hW2, hb2, base_wp, base_wn, base_bn);
            }
        }

        // compute on smem[p]: 4 k8 steps
#pragma unroll
        for (int ks = 0; ks < 4; ks++) {
            int kb = ks * 8;
            float a[2][4];
            float bf[4][2];
#pragma unroll
            for (int mi = 0; mi < 2; mi++) {
                a[mi][0] = As[p][kb + t][mw + 16 * mi + g];
                a[mi][1] = As[p][kb + t][mw + 16 * mi + g + 8];
                a[mi][2] = As[p][kb + t + 4][mw + 16 * mi + g];
                a[mi][3] = As[p][kb + t + 4][mw + 16 * mi + g + 8];
            }
#pragma unroll
            for (int ni = 0; ni < 4; ni++) {
                bf[ni][0] = Bs[p][kb + t][nw + 8 * ni + g];
                bf[ni][1] = Bs[p][kb + t + 4][nw + 8 * ni + g];
            }
#pragma unroll
            for (int mi = 0; mi < 2; mi++)
#pragma unroll
                for (int ni = 0; ni < 4; ni++)
                    mma_tf32(acc[mi][ni], a[mi], bf[ni]);
        }
        p ^= 1;
    }

    // write partials
    float* pre = g_pre + kspl * (BATCH * NCOL);
    const int rowb = mt * BM + mw;
    const int colb = nt * BN + nw;
#pragma unroll
    for (int mi = 0; mi < 2; mi++) {
#pragma unroll
        for (int ni = 0; ni < 4; ni++) {
            int row = rowb + 16 * mi + g;
            int col = colb + 8 * ni + 2 * t;
            pre[row * NCOL + col]           = acc[mi][ni][0];
            pre[row * NCOL + col + 1]       = acc[mi][ni][1];
            pre[(row + 8) * NCOL + col]     = acc[mi][ni][2];
            pre[(row + 8) * NCOL + col + 1] = acc[mi][ni][3];
        }
    }
}

// ---------------- kernel 4: epilogue (split-K sum, cos/sin/relu, gating) ----------------
__global__ void epi_kernel(float* __restrict__ out) {
    int b = blockIdx.x;
    int c = threadIdx.x;
    __shared__ float gws[NEXP];
    if (c < NEXP) gws[c] = g_gw[b * NEXP + c];
    __syncthreads();

    const float* p0 = g_pre + b * NCOL;
    const float* p1 = g_pre + BATCH * NCOL + b * NCOL;

    if (c < 64) {
        float sc = 0.f, ss = 0.f;
#pragma unroll
        for (int e = 0; e < NEXP; e++) {
            float v = p0[e * 192 + c] + p1[e * 192 + c];
            float s, co;
            sincosf(v, &s, &co);
            sc += gws[e] * co;
            ss += gws[e] * s;
        }
        out[b * 256 + c]      = sc;
        out[b * 256 + 64 + c] = ss;
    } else if (c < 192) {
        int q = c - 64;
        float sn = 0.f;
#pragma unroll
        for (int e = 0; e < NEXP; e++) {
            float v = p0[e * 192 + 64 + q] + p1[e * 192 + 64 + q];
            sn += gws[e] * fmaxf(v, 0.f);
        }
        out[b * 256 + 128 + q] = sn;
    }
}

// ---------------- launch ----------------
extern "C" void kernel_launch(void* const* d_in, const int* in_sizes, int n_in,
                              void* d_out, int out_size) {
    const float* x       = (const float*)d_in[0];
    const float* cond    = (const float*)d_in[1];
    const float* base_wp = (const float*)d_in[2];
    const float* base_wn = (const float*)d_in[3];
    const float* base_bn = (const float*)d_in[4];
    const float* hW1     = (const float*)d_in[5];
    const float* hb1     = (const float*)d_in[6];
    const float* hW2     = (const float*)d_in[7];
    const float* hb2     = (const float*)d_in[8];
    const float* gW1     = (const float*)d_in[9];
    const float* gb1     = (const float*)d_in[10];
    const float* gW2     = (const float*)d_in[11];
    const float* gb2     = (const float*)d_in[12];
    float* out = (float*)d_out;

    head_kernel<<<BATCH, 128>>>(cond, hW1, hb1, gW1, gb1, gW2, gb2);

    packA_kernel<<<(KP * (BATCH / 4)) / 256, 256>>>(x);

    dim3 gg(NCOL / BN, BATCH / BM, 2);
    gemm_kernel<<<gg, 128>>>(hW2, hb2, base_wp, base_wn, base_bn);

    epi_kernel<<<BATCH, 192>>>(out);
}

// round 9
// speedup vs baseline: 1.4017x; 1.4017x over previous
#include <cuda_runtime.h>
#include <cstdint>
#include <math.h>

// Problem constants
#define BATCH  512
#define INDIM  256
#define CONDD  128
#define NEXP   8
#define HD     64
#define DP     64
#define DN     128
#define TPE    49280      // INDIM*DP + INDIM*DN + DN
#define TOTALW 394240     // NEXP*TPE
#define NCOL   1536       // NEXP*(DP+DN)

// GEMM K layout:
//  [0,16384)      : A = h[b,hh]*x[b,i]  (k = hh*256 + i)  <-> B = hW2 wp/wn slices (read IN PLACE)
//  [16384,16640)  : A = x[b,i]                            <-> B = base_wp/base_wn + hb2   (tail)
//  [16640,16704)  : A = h[b,hh]                           <-> B = hW2 bn slice           (tail)
//  16704          : A = 1.0                               <-> B = base_bn + hb2 bn       (tail)
//  [16705,16736)  : zero pad                                                             (tail)
#define KP       16736
#define KTAIL    352      // KP - 16384
#define NSPLIT   3

#define BM 128
#define BN 128
#define BK 32
#define STAGES 3
#define LDSR 136                 // row stride (mod 32 == 8 -> conflict-free frags)
#define SLAB (2 * BK * LDSR)     // floats per pipeline stage (A tile + B tile)

// ---------------- scratch (no allocation allowed) ----------------
__device__ float g_h[BATCH * HD];
__device__ float g_gw[BATCH * NEXP];
__device__ float g_At[KP * BATCH];            // A^T [k][b], tf32-rounded (34.3 MB, L2-resident)
__device__ float g_Btail[KTAIL * NCOL];       // packed bias tail rows (2.2 MB)
__device__ float g_pre[NSPLIT * BATCH * NCOL];// split-K partials

__device__ __forceinline__ float tf32r(float x) {
    float y;
    asm("cvt.rna.tf32.f32 %0, %1;" : "=f"(y) : "f"(x));
    return y;
}
__device__ __forceinline__ void cp16(unsigned int dst, const float* src) {
    asm volatile("cp.async.cg.shared.global [%0], [%1], 16;\n" :: "r"(dst), "l"(src));
}

// m16n8k8 tf32 warp MMA
__device__ __forceinline__ void mma_tf32(float* d, const float* a, const float* b) {
    const unsigned int* A  = reinterpret_cast<const unsigned int*>(a);
    const unsigned int* Bv = reinterpret_cast<const unsigned int*>(b);
    asm volatile(
        "mma.sync.aligned.m16n8k8.row.col.f32.tf32.tf32.f32 "
        "{%0,%1,%2,%3}, {%4,%5,%6,%7}, {%8,%9}, {%0,%1,%2,%3};\n"
        : "+f"(d[0]), "+f"(d[1]), "+f"(d[2]), "+f"(d[3])
        : "r"(A[0]), "r"(A[1]), "r"(A[2]), "r"(A[3]), "r"(Bv[0]), "r"(Bv[1]));
}

// ---------------- kernel 1: cond head (h + gates) ----------------
__global__ void head_kernel(const float* __restrict__ cond,
                            const float* __restrict__ hW1, const float* __restrict__ hb1,
                            const float* __restrict__ gW1, const float* __restrict__ gb1,
                            const float* __restrict__ gW2, const float* __restrict__ gb2) {
    int b = blockIdx.x;
    int tid = threadIdx.x;
    __shared__ float cs[CONDD];
    __shared__ float ts[24];
    __shared__ float lg[NEXP];

    cs[tid] = cond[b * CONDD + tid];
    __syncthreads();

    if (tid < HD) {
        float acc = hb1[tid];
#pragma unroll 8
        for (int i = 0; i < CONDD; i++) acc += cs[i] * hW1[i * HD + tid];
        g_h[b * HD + tid] = fmaxf(acc, 0.f);
    } else if (tid < HD + 24) {
        int j = tid - HD;
        float acc = gb1[j];
#pragma unroll 8
        for (int i = 0; i < CONDD; i++) acc += cs[i] * gW1[i * 24 + j];
        ts[j] = fmaxf(acc, 0.f);
    }
    __syncthreads();

    if (tid < NEXP) {
        float acc = gb2[tid];
#pragma unroll
        for (int t = 0; t < 24; t++) acc += ts[t] * gW2[t * NEXP + tid];
        lg[tid] = acc;
    }
    __syncthreads();

    if (tid == 0) {
        float mx = lg[0];
#pragma unroll
        for (int e = 1; e < NEXP; e++) mx = fmaxf(mx, lg[e]);
        float ex[NEXP];
        float s = 0.f;
#pragma unroll
        for (int e = 0; e < NEXP; e++) { ex[e] = expf(lg[e] - mx); s += ex[e]; }
        float inv = 1.f / s;
#pragma unroll
        for (int e = 0; e < NEXP; e++) g_gw[b * NEXP + e] = ex[e] * inv;
    }
}

// ---------------- kernel 2: pack A^T [KP][BATCH], tf32-rounded ----------------
__global__ void packA_kernel(const float* __restrict__ x) {
    int idx = blockIdx.x * blockDim.x + threadIdx.x;   // one float4 over b
    int k = idx >> 7;
    int b0 = (idx & 127) << 2;
    float v[4];
    if (k < 16384) {
        int hh = k >> 8, i = k & 255;
#pragma unroll
        for (int r = 0; r < 4; r++)
            v[r] = g_h[(b0 + r) * HD + hh] * x[(b0 + r) * INDIM + i];
    } else if (k < 16640) {
        int i = k - 16384;
#pragma unroll
        for (int r = 0; r < 4; r++) v[r] = x[(b0 + r) * INDIM + i];
    } else if (k < 16704) {
        int hh = k - 16640;
#pragma unroll
        for (int r = 0; r < 4; r++) v[r] = g_h[(b0 + r) * HD + hh];
    } else if (k == 16704) {
#pragma unroll
        for (int r = 0; r < 4; r++) v[r] = 1.0f;
    } else {
#pragma unroll
        for (int r = 0; r < 4; r++) v[r] = 0.0f;
    }
    float4 o;
    o.x = tf32r(v[0]); o.y = tf32r(v[1]); o.z = tf32r(v[2]); o.w = tf32r(v[3]);
    *reinterpret_cast<float4*>(&g_At[k * BATCH + b0]) = o;
}

// ---------------- kernel 2b: pack the 352 bias-tail rows of B ----------------
__global__ void packTail_kernel(const float* __restrict__ hW2, const float* __restrict__ hb2,
                                const float* __restrict__ base_wp, const float* __restrict__ base_wn,
                                const float* __restrict__ base_bn) {
    int idx = blockIdx.x * blockDim.x + threadIdx.x;   // KTAIL*NCOL = 540672
    int kt = idx / NCOL;
    int col = idx - kt * NCOL;
    int k = 16384 + kt;
    int q = col >> 6, cl = col & 63;
    int n = q / 3, rr = q % 3;
    float v = 0.f;
    if (k < 16640) {
        int i = k - 16384;
        if (rr == 0)
            v = base_wp[(n * INDIM + i) * DP + cl] + hb2[n * TPE + i * DP + cl];
        else {
            int j = (rr - 1) * 64 + cl;
            v = base_wn[(n * INDIM + i) * DN + j] + hb2[n * TPE + INDIM * DP + i * DN + j];
        }
    } else if (k < 16704) {
        if (rr) {
            int hh = k - 16640;
            int j = (rr - 1) * 64 + cl;
            v = hW2[(size_t)hh * TOTALW + n * TPE + INDIM * (DP + DN) + j];
        }
    } else if (k == 16704) {
        if (rr) {
            int j = (rr - 1) * 64 + cl;
            v = base_bn[n * DN + j] + hb2[n * TPE + INDIM * (DP + DN) + j];
        }
    }
    g_Btail[kt * NCOL + col] = tf32r(v);
}

// ---------------- GEMM stage loader (cp.async, A + B direct-from-hW2) -------
__device__ __forceinline__ void stage_issue(
    int ktile, int s, unsigned int smb,
    const float* At_src, const float* Bt_src,
    const float* hW2, size_t bcol0, int imul, int lr, int lc)
{
    const int kb0 = ktile * BK;
    const unsigned int ao = smb + (unsigned int)(s * SLAB * 4);
    const unsigned int bo = ao + (unsigned int)(BK * LDSR * 4);
#pragma unroll
    for (int it = 0; it < 4; it++) {
        const int kk = lr + it * 8;
        const int k = kb0 + kk;
        cp16(ao + (unsigned int)((kk * LDSR + lc) * 4), At_src + (size_t)k * BATCH);
        const float* bs;
        if (k < 16384)
            bs = hW2 + (size_t)(k >> 8) * TOTALW + bcol0 + (size_t)(k & 255) * imul;
        else
            bs = Bt_src + (size_t)(k - 16384) * NCOL;
        cp16(bo + (unsigned int)((kk * LDSR + lc) * 4), bs);
    }
}

// ---------------- kernel 3: 128x128x32 GEMM, 3-stage cp.async, split-K=3 ----
__global__ void __launch_bounds__(256, 1) gemm_kernel(const float* __restrict__ hW2) {
    extern __shared__ float sm[];
    const int tid  = threadIdx.x;
    const int lane = tid & 31, warp = tid >> 5;
    const int g = lane >> 2, t = lane & 3;
    const int mw = (warp >> 2) * 64;     // 2 warps in M
    const int nw = (warp & 3) * 32;      // 4 warps in N

    const int mt   = blockIdx.x & 3;     // x-fastest: same-nt CTAs adjacent -> B L2 reuse
    const int kspl = blockIdx.x >> 2;
    const int nt   = blockIdx.y;

    const int kt0 = (kspl == 0) ? 0 : ((kspl == 1) ? 175 : 349);
    const int nk  = (kspl == 0) ? 175 : 174;

    // loader geometry: 8 rows x 32 float4-cols per pass, 4 passes per tile
    const int lr = tid >> 5;
    const int lc = (tid & 31) * 4;
    const int q  = 2 * nt + (lc >> 6);   // 64-col group id
    const int cl = lc & 63;
    const int qn = q / 3, qr = q % 3;
    const size_t bcol0 = (size_t)qn * TPE +
        ((qr == 0) ? (size_t)cl : (size_t)(INDIM * DP + (qr - 1) * 64 + cl));
    const int imul = (qr == 0) ? DP : DN;
    const float* At_src = g_At + mt * BM + lc;
    const float* Bt_src = g_Btail + q * 64 + cl;

    const unsigned int smb = (unsigned int)__cvta_generic_to_shared(sm);

    // prologue: stages 0..STAGES-2
#pragma unroll
    for (int s = 0; s < STAGES - 1; s++) {
        stage_issue(kt0 + s, s, smb, At_src, Bt_src, hW2, bcol0, imul, lr, lc);
        asm volatile("cp.async.commit_group;\n");
    }

    float acc[4][4][4];
#pragma unroll
    for (int mi = 0; mi < 4; mi++)
#pragma unroll
        for (int ni = 0; ni < 4; ni++)
#pragma unroll
            for (int e = 0; e < 4; e++) acc[mi][ni][e] = 0.f;

    for (int kt = 0; kt < nk; kt++) {
        asm volatile("cp.async.wait_group %0;\n" :: "n"(STAGES - 2));
        __syncthreads();   // stage kt landed; everyone done computing stage kt-1's buffer

        const int pf = kt + STAGES - 1;
        if (pf < nk)
            stage_issue(kt0 + pf, pf % STAGES, smb, At_src, Bt_src, hW2, bcol0, imul, lr, lc);
        asm volatile("cp.async.commit_group;\n");

        const float* As = sm + (kt % STAGES) * SLAB;
        const float* Bs = As + BK * LDSR;

#pragma unroll
        for (int ks = 0; ks < 4; ks++) {
            const int kb = ks * 8;
            float a[4][4], bf[4][2];
#pragma unroll
            for (int mi = 0; mi < 4; mi++) {
                a[mi][0] = As[(kb + t) * LDSR + mw + 16 * mi + g];
                a[mi][1] = As[(kb + t) * LDSR + mw + 16 * mi + g + 8];
                a[mi][2] = As[(kb + t + 4) * LDSR + mw + 16 * mi + g];
                a[mi][3] = As[(kb + t + 4) * LDSR + mw + 16 * mi + g + 8];
            }
#pragma unroll
            for (int ni = 0; ni < 4; ni++) {
                bf[ni][0] = Bs[(kb + t) * LDSR + nw + 8 * ni + g];
                bf[ni][1] = Bs[(kb + t + 4) * LDSR + nw + 8 * ni + g];
            }
#pragma unroll
            for (int mi = 0; mi < 4; mi++)
#pragma unroll
                for (int ni = 0; ni < 4; ni++)
                    mma_tf32(acc[mi][ni], a[mi], bf[ni]);
        }
    }

    // write split-K partials
    float* pre = g_pre + (size_t)kspl * (BATCH * NCOL);
    const int rowb = mt * BM + mw;
    const int colb = nt * BN + nw;
#pragma unroll
    for (int mi = 0; mi < 4; mi++) {
#pragma unroll
        for (int ni = 0; ni < 4; ni++) {
            int row = rowb + 16 * mi + g;
            int col = colb + 8 * ni + 2 * t;
            pre[row * NCOL + col]           = acc[mi][ni][0];
            pre[row * NCOL + col + 1]       = acc[mi][ni][1];
            pre[(row + 8) * NCOL + col]     = acc[mi][ni][2];
            pre[(row + 8) * NCOL + col + 1] = acc[mi][ni][3];
        }
    }
}

// ---------------- kernel 4: epilogue (split-K sum, cos/sin/relu, gating) ----
__global__ void epi_kernel(float* __restrict__ out) {
    int b = blockIdx.x;
    int c = threadIdx.x;
    __shared__ float gws[NEXP];
    if (c < NEXP) gws[c] = g_gw[b * NEXP + c];
    __syncthreads();

    const float* p0 = g_pre + b * NCOL;
    const float* p1 = p0 + BATCH * NCOL;
    const float* p2 = p1 + BATCH * NCOL;

    if (c < 64) {
        float sc = 0.f, ss = 0.f;
#pragma unroll
        for (int e = 0; e < NEXP; e++) {
            int o = e * 192 + c;
            float v = p0[o] + p1[o] + p2[o];
            float s, co;
            sincosf(v, &s, &co);
            sc += gws[e] * co;
            ss += gws[e] * s;
        }
        out[b * 256 + c]      = sc;
        out[b * 256 + 64 + c] = ss;
    } else if (c < 192) {
        int qq = c - 64;
        float sn = 0.f;
#pragma unroll
        for (int e = 0; e < NEXP; e++) {
            int o = e * 192 + 64 + qq;
            float v = p0[o] + p1[o] + p2[o];
            sn += gws[e] * fmaxf(v, 0.f);
        }
        out[b * 256 + 128 + qq] = sn;
    }
}

// ---------------- launch ----------------
extern "C" void kernel_launch(void* const* d_in, const int* in_sizes, int n_in,
                              void* d_out, int out_size) {
    const float* x       = (const float*)d_in[0];
    const float* cond    = (const float*)d_in[1];
    const float* base_wp = (const float*)d_in[2];
    const float* base_wn = (const float*)d_in[3];
    const float* base_bn = (const float*)d_in[4];
    const float* hW1     = (const float*)d_in[5];
    const float* hb1     = (const float*)d_in[6];
    const float* hW2     = (const float*)d_in[7];
    const float* hb2     = (const float*)d_in[8];
    const float* gW1     = (const float*)d_in[9];
    const float* gb1     = (const float*)d_in[10];
    const float* gW2     = (const float*)d_in[11];
    const float* gb2     = (const float*)d_in[12];
    float* out = (float*)d_out;

    cudaFuncSetAttribute(gemm_kernel, cudaFuncAttributeMaxDynamicSharedMemorySize,
                         STAGES * SLAB * 4);

    head_kernel<<<BATCH, 128>>>(cond, hW1, hb1, gW1, gb1, gW2, gb2);

    packA_kernel<<<(KP * (BATCH / 4)) / 256, 256>>>(x);

    packTail_kernel<<<(KTAIL * NCOL) / 256, 256>>>(hW2, hb2, base_wp, base_wn, base_bn);

    dim3 gg(4 * NSPLIT, NCOL / BN);   // x = mt + 4*kspl (12), y = nt (12)
    gemm_kernel<<<gg, 256, STAGES * SLAB * 4>>>(hW2);

    epi_kernel<<<BATCH, 192>>>(out);
}

// round 10
// speedup vs baseline: 1.9328x; 1.3789x over previous
#include <cuda_runtime.h>
#include <cstdint>
#include <math.h>

// Problem constants
#define BATCH  512
#define INDIM  256
#define CONDD  128
#define NEXP   8
#define HD     64
#define DP     64
#define DN     128
#define TPE    49280      // INDIM*DP + INDIM*DN + DN
#define TOTALW 394240     // NEXP*TPE
#define NCOL   1536       // NEXP*(DP+DN)

// GEMM K layout:
//  [0,16384)      : A = h[b,hh]*x[b,i]  (k = hh*256 + i)  <-> B = hW2 wp/wn slices (in place)
//  [16384,16640)  : A = x[b,i]                            <-> B = base_wp/wn + hb2   (tail)
//  [16640,16704)  : A = h[b,hh]                           <-> B = hW2 bn slice       (tail)
//  16704          : A = 1.0                               <-> B = base_bn + hb2 bn   (tail)
//  [16705,16736)  : zero pad                                                         (tail)
#define KP       16736
#define KTAIL    352
#define KTILES   523      // KP/32
#define NSPLIT   6

#define BM 128
#define BN 128
#define BK 32
#define STAGES 3
#define ASLAB 4096               // A tile floats (fragment-ordered, contiguous)
#define LDSR 136                 // B row stride (mod 32 == 8 -> conflict-free)
#define BSLAB (BK * LDSR)        // 4352 floats
#define SLAB (ASLAB + BSLAB)     // 8448 floats per stage

// ---------------- scratch ----------------
__device__ float g_h[BATCH * HD];
__device__ float g_gw[BATCH * NEXP];
// A in MMA-fragment order: [ktile 523][mtile 4][ks 4][mblk 8][lane 32][slot 4]
__device__ float g_At[KTILES * 4 * ASLAB];
__device__ float g_Btail[KTAIL * NCOL];
__device__ float g_pre[NSPLIT * BATCH * NCOL];

__device__ __forceinline__ float tf32r(float x) {
    float y;
    asm("cvt.rna.tf32.f32 %0, %1;" : "=f"(y) : "f"(x));
    return y;
}
__device__ __forceinline__ void cp16(unsigned int dst, const float* src) {
    asm volatile("cp.async.cg.shared.global [%0], [%1], 16;\n" :: "r"(dst), "l"(src));
}

// m16n8k8 tf32 warp MMA
__device__ __forceinline__ void mma_tf32(float* d, const float* a, const float* b) {
    const unsigned int* A  = reinterpret_cast<const unsigned int*>(a);
    const unsigned int* Bv = reinterpret_cast<const unsigned int*>(b);
    asm volatile(
        "mma.sync.aligned.m16n8k8.row.col.f32.tf32.tf32.f32 "
        "{%0,%1,%2,%3}, {%4,%5,%6,%7}, {%8,%9}, {%0,%1,%2,%3};\n"
        : "+f"(d[0]), "+f"(d[1]), "+f"(d[2]), "+f"(d[3])
        : "r"(A[0]), "r"(A[1]), "r"(A[2]), "r"(A[3]), "r"(Bv[0]), "r"(Bv[1]));
}

// ---------------- kernel 1: cond head (h + gates) ----------------
__global__ void head_kernel(const float* __restrict__ cond,
                            const float* __restrict__ hW1, const float* __restrict__ hb1,
                            const float* __restrict__ gW1, const float* __restrict__ gb1,
                            const float* __restrict__ gW2, const float* __restrict__ gb2) {
    int b = blockIdx.x;
    int tid = threadIdx.x;
    __shared__ float cs[CONDD];
    __shared__ float ts[24];
    __shared__ float lg[NEXP];

    cs[tid] = cond[b * CONDD + tid];
    __syncthreads();

    if (tid < HD) {
        float acc = hb1[tid];
#pragma unroll 8
        for (int i = 0; i < CONDD; i++) acc += cs[i] * hW1[i * HD + tid];
        g_h[b * HD + tid] = fmaxf(acc, 0.f);
    } else if (tid < HD + 24) {
        int j = tid - HD;
        float acc = gb1[j];
#pragma unroll 8
        for (int i = 0; i < CONDD; i++) acc += cs[i] * gW1[i * 24 + j];
        ts[j] = fmaxf(acc, 0.f);
    }
    __syncthreads();

    if (tid < NEXP) {
        float acc = gb2[tid];
#pragma unroll
        for (int t = 0; t < 24; t++) acc += ts[t] * gW2[t * NEXP + tid];
        lg[tid] = acc;
    }
    __syncthreads();

    if (tid == 0) {
        float mx = lg[0];
#pragma unroll
        for (int e = 1; e < NEXP; e++) mx = fmaxf(mx, lg[e]);
        float ex[NEXP];
        float s = 0.f;
#pragma unroll
        for (int e = 0; e < NEXP; e++) { ex[e] = expf(lg[e] - mx); s += ex[e]; }
        float inv = 1.f / s;
#pragma unroll
        for (int e = 0; e < NEXP; e++) g_gw[b * NEXP + e] = ex[e] * inv;
    }
}

// A element (k, b) of the virtual A^T matrix
__device__ __forceinline__ float aval(int k, int b, const float* __restrict__ x) {
    if (k < 16384) return g_h[b * HD + (k >> 8)] * x[b * INDIM + (k & 255)];
    if (k < 16640) return x[b * INDIM + (k - 16384)];
    if (k < 16704) return g_h[b * HD + (k - 16640)];
    if (k == 16704) return 1.0f;
    return 0.0f;
}

// ---------------- kernel 2: pack A in fragment order (one float4 per thread) --
__global__ void packA_kernel(const float* __restrict__ x) {
    int f = blockIdx.x * blockDim.x + threadIdx.x;   // float4 index, total 2,142,208
    int tile   = f >> 10;           // 1024 float4 per (ktile,mtile) tile
    int within = f & 1023;
    int ktile = tile >> 2;
    int mtile = tile & 3;
    int ks   = within >> 8;
    int rem  = within & 255;
    int mblk = rem >> 5;
    int lane = rem & 31;
    int g = lane >> 2, t = lane & 3;
    int k0 = ktile * 32 + ks * 8 + t;
    int m0 = mtile * 128 + mblk * 16 + g;

    float4 o;
    o.x = tf32r(aval(k0,     m0,     x));
    o.y = tf32r(aval(k0,     m0 + 8, x));
    o.z = tf32r(aval(k0 + 4, m0,     x));
    o.w = tf32r(aval(k0 + 4, m0 + 8, x));
    reinterpret_cast<float4*>(g_At)[f] = o;
}

// ---------------- kernel 2b: pack the 352 bias-tail rows of B ----------------
__global__ void packTail_kernel(const float* __restrict__ hW2, const float* __restrict__ hb2,
                                const float* __restrict__ base_wp, const float* __restrict__ base_wn,
                                const float* __restrict__ base_bn) {
    int idx = blockIdx.x * blockDim.x + threadIdx.x;   // KTAIL*NCOL
    int kt = idx / NCOL;
    int col = idx - kt * NCOL;
    int k = 16384 + kt;
    int q = col >> 6, cl = col & 63;
    int n = q / 3, rr = q % 3;
    float v = 0.f;
    if (k < 16640) {
        int i = k - 16384;
        if (rr == 0)
            v = base_wp[(n * INDIM + i) * DP + cl] + hb2[n * TPE + i * DP + cl];
        else {
            int j = (rr - 1) * 64 + cl;
            v = base_wn[(n * INDIM + i) * DN + j] + hb2[n * TPE + INDIM * DP + i * DN + j];
        }
    } else if (k < 16704) {
        if (rr) {
            int hh = k - 16640;
            int j = (rr - 1) * 64 + cl;
            v = hW2[(size_t)hh * TOTALW + n * TPE + INDIM * (DP + DN) + j];
        }
    } else if (k == 16704) {
        if (rr) {
            int j = (rr - 1) * 64 + cl;
            v = base_bn[n * DN + j] + hb2[n * TPE + INDIM * (DP + DN) + j];
        }
    }
    g_Btail[kt * NCOL + col] = tf32r(v);
}

// ---------------- GEMM stage loader ----------------
__device__ __forceinline__ void stage_issue(
    int ktile, int s, unsigned int smb, int tid,
    const float* Asrc_base,             // g_At + mt*ASLAB
    const float* Bt_src,
    const float* hW2, size_t bcol0, int imul, int lr, int lc)
{
    const unsigned int ao = smb + (unsigned int)(s * SLAB * 4);
    const unsigned int bo = ao + (unsigned int)(ASLAB * 4);
    // A: contiguous 16 KB block, perfectly coalesced
    const float* Asrc = Asrc_base + (size_t)ktile * (4 * ASLAB);
#pragma unroll
    for (int j = 0; j < 4; j++) {
        int f4 = tid + j * 256;
        cp16(ao + (unsigned int)(f4 * 16), Asrc + f4 * 4);
    }
    // B: 8 rows x 32 float4 per pass, 4 passes
    const int kb0 = ktile * BK;
#pragma unroll
    for (int it = 0; it < 4; it++) {
        const int kk = lr + it * 8;
        const int k = kb0 + kk;
        const float* bs;
        if (k < 16384)
            bs = hW2 + (size_t)(k >> 8) * TOTALW + bcol0 + (size_t)(k & 255) * imul;
        else
            bs = Bt_src + (size_t)(k - 16384) * NCOL;
        cp16(bo + (unsigned int)((kk * LDSR + lc) * 4), bs);
    }
}

// ---------------- kernel 3: 128x128x32 GEMM, vectorized A frags, 2 CTAs/SM ---
__global__ void __launch_bounds__(256, 2) gemm_kernel(const float* __restrict__ hW2) {
    extern __shared__ float sm[];
    const int tid  = threadIdx.x;
    const int lane = tid & 31, warp = tid >> 5;
    const int g = lane >> 2, t = lane & 3;
    const int mw = (warp >> 2) * 64;     // 2 warps in M
    const int nw = (warp & 3) * 32;      // 4 warps in N
    const int mb0 = (warp >> 2) * 4;     // mblk base

    const int mt   = blockIdx.x & 3;     // x-fastest: same-nt CTAs adjacent -> B L2 reuse
    const int kspl = blockIdx.x >> 2;
    const int nt   = blockIdx.y;

    const int kt0 = kspl * 87 + (kspl ? 1 : 0);   // splits: 88,87,87,87,87,87
    const int nk  = (kspl == 0) ? 88 : 87;

    // B loader geometry
    const int lr = tid >> 5;
    const int lc = (tid & 31) * 4;
    const int q  = 2 * nt + (lc >> 6);
    const int cl = lc & 63;
    const int qn = q / 3, qr = q % 3;
    const size_t bcol0 = (size_t)qn * TPE +
        ((qr == 0) ? (size_t)cl : (size_t)(INDIM * DP + (qr - 1) * 64 + cl));
    const int imul = (qr == 0) ? DP : DN;
    const float* Asrc_base = g_At + (size_t)mt * ASLAB;
    const float* Bt_src = g_Btail + q * 64 + cl;

    const unsigned int smb = (unsigned int)__cvta_generic_to_shared(sm);

#pragma unroll
    for (int s = 0; s < STAGES - 1; s++) {
        stage_issue(kt0 + s, s, smb, tid, Asrc_base, Bt_src, hW2, bcol0, imul, lr, lc);
        asm volatile("cp.async.commit_group;\n");
    }

    float acc[4][4][4];
#pragma unroll
    for (int mi = 0; mi < 4; mi++)
#pragma unroll
        for (int ni = 0; ni < 4; ni++)
#pragma unroll
            for (int e = 0; e < 4; e++) acc[mi][ni][e] = 0.f;

    for (int kt = 0; kt < nk; kt++) {
        asm volatile("cp.async.wait_group %0;\n" :: "n"(STAGES - 2));
        __syncthreads();

        const int pf = kt + STAGES - 1;
        if (pf < nk)
            stage_issue(kt0 + pf, pf % STAGES, smb, tid, Asrc_base, Bt_src,
                        hW2, bcol0, imul, lr, lc);
        asm volatile("cp.async.commit_group;\n");

        const float* As = sm + (kt % STAGES) * SLAB;
        const float* Bs = As + ASLAB;
        const float4* Af = reinterpret_cast<const float4*>(As);

#pragma unroll
        for (int ks = 0; ks < 4; ks++) {
            const int kb = ks * 8;
            float4 a4[4];
            float bf[4][2];
#pragma unroll
            for (int mi = 0; mi < 4; mi++)
                a4[mi] = Af[(ks * 8 + mb0 + mi) * 32 + lane];   // LDS.128, conflict-free
#pragma unroll
            for (int ni = 0; ni < 4; ni++) {
                bf[ni][0] = Bs[(kb + t) * LDSR + nw + 8 * ni + g];
                bf[ni][1] = Bs[(kb + t + 4) * LDSR + nw + 8 * ni + g];
            }
#pragma unroll
            for (int mi = 0; mi < 4; mi++)
#pragma unroll
                for (int ni = 0; ni < 4; ni++)
                    mma_tf32(acc[mi][ni], reinterpret_cast<float*>(&a4[mi]), bf[ni]);
        }
    }

    // write split-K partials
    float* pre = g_pre + (size_t)kspl * (BATCH * NCOL);
    const int rowb = mt * BM + mw;
    const int colb = nt * BN + nw;
#pragma unroll
    for (int mi = 0; mi < 4; mi++) {
#pragma unroll
        for (int ni = 0; ni < 4; ni++) {
            int row = rowb + 16 * mi + g;
            int col = colb + 8 * ni + 2 * t;
            pre[row * NCOL + col]           = acc[mi][ni][0];
            pre[row * NCOL + col + 1]       = acc[mi][ni][1];
            pre[(row + 8) * NCOL + col]     = acc[mi][ni][2];
            pre[(row + 8) * NCOL + col + 1] = acc[mi][ni][3];
        }
    }
}

// ---------------- kernel 4: epilogue ----------------
__global__ void epi_kernel(float* __restrict__ out) {
    int b = blockIdx.x;
    int c = threadIdx.x;
    __shared__ float gws[NEXP];
    if (c < NEXP) gws[c] = g_gw[b * NEXP + c];
    __syncthreads();

    const float* p = g_pre + b * NCOL;
    const size_t STRIDE = (size_t)BATCH * NCOL;

    if (c < 64) {
        float sc = 0.f, ss = 0.f;
#pragma unroll
        for (int e = 0; e < NEXP; e++) {
            int o = e * 192 + c;
            float v = 0.f;
#pragma unroll
            for (int s = 0; s < NSPLIT; s++) v += p[s * STRIDE + o];
            float sn, co;
            sincosf(v, &sn, &co);
            sc += gws[e] * co;
            ss += gws[e] * sn;
        }
        out[b * 256 + c]      = sc;
        out[b * 256 + 64 + c] = ss;
    } else if (c < 192) {
        int qq = c - 64;
        float snn = 0.f;
#pragma unroll
        for (int e = 0; e < NEXP; e++) {
            int o = e * 192 + 64 + qq;
            float v = 0.f;
#pragma unroll
            for (int s = 0; s < NSPLIT; s++) v += p[s * STRIDE + o];
            snn += gws[e] * fmaxf(v, 0.f);
        }
        out[b * 256 + 128 + qq] = snn;
    }
}

// ---------------- launch ----------------
extern "C" void kernel_launch(void* const* d_in, const int* in_sizes, int n_in,
                              void* d_out, int out_size) {
    const float* x       = (const float*)d_in[0];
    const float* cond    = (const float*)d_in[1];
    const float* base_wp = (const float*)d_in[2];
    const float* base_wn = (const float*)d_in[3];
    const float* base_bn = (const float*)d_in[4];
    const float* hW1     = (const float*)d_in[5];
    const float* hb1     = (const float*)d_in[6];
    const float* hW2     = (const float*)d_in[7];
    const float* hb2     = (const float*)d_in[8];
    const float* gW1     = (const float*)d_in[9];
    const float* gb1     = (const float*)d_in[10];
    const float* gW2     = (const float*)d_in[11];
    const float* gb2     = (const float*)d_in[12];
    float* out = (float*)d_out;

    cudaFuncSetAttribute(gemm_kernel, cudaFuncAttributeMaxDynamicSharedMemorySize,
                         STAGES * SLAB * 4);

    head_kernel<<<BATCH, 128>>>(cond, hW1, hb1, gW1, gb1, gW2, gb2);

    // 2,142,208 float4 outputs / 256 threads
    packA_kernel<<<(KTILES * 4 * ASLAB / 4) / 256, 256>>>(x);

    packTail_kernel<<<(KTAIL * NCOL) / 256, 256>>>(hW2, hb2, base_wp, base_wn, base_bn);

    dim3 gg(4 * NSPLIT, NCOL / BN);   // x = mt + 4*kspl (24), y = nt (12) -> 288 CTAs
    gemm_kernel<<<gg, 256, STAGES * SLAB * 4>>>(hW2);

    epi_kernel<<<BATCH, 192>>>(out);
}

// round 14
// speedup vs baseline: 2.2653x; 1.1720x over previous
#include <cuda_runtime.h>
#include <cuda_fp16.h>
#include <cstdint>
#include <math.h>

// Problem constants
#define BATCH  512
#define INDIM  256
#define CONDD  128
#define NEXP   8
#define HD     64
#define DP     64
#define DN     128
#define TPE    49280
#define TOTALW 394240
#define NCOL   1536

// K layout: [0,16384) h*x | [16384,16640) x | [16640,16704) h | 16704 ones | pad
#define KP      16736
#define KTILES  523      // KP/32
#define NSPLIT  6

#define BM 128
#define BN 128
#define BK 32
#define STAGES 4
#define ABYTES 8192              // A stage: 512 uint4 fragments
#define BROWW  20                // B smem words per n row (16 used + 4 pad; conflict-free)
#define BBYTES (BM * BROWW * 4)  // 10240
#define SLABB  (ABYTES + BBYTES) // 18432

// ---------------- scratch ----------------
__device__ float g_h[BATCH * HD];
__device__ float g_gw[BATCH * NEXP];
// A fp16, MMA-fragment order: [ktile][mtile 4][ks 2][mblk 8][lane 32] x uint4 (17.1 MB)
__device__ uint4 g_Ah[(size_t)KTILES * 4 * 512];
// B fp16, k-pair order: [ktile][n 1536][16 half2] (51.4 MB)
__device__ uint4 g_Bh[(size_t)KTILES * 1536 * 4];
__device__ float g_pre[(size_t)NSPLIT * BATCH * NCOL];

__device__ __forceinline__ void cp16(unsigned dst, const void* src) {
    asm volatile("cp.async.cg.shared.global [%0], [%1], 16;\n" :: "r"(dst), "l"(src));
}
__device__ __forceinline__ unsigned smem_u32(const void* p) {
    unsigned a;
    asm("{ .reg .u64 t; cvta.to.shared.u64 t, %1; cvt.u32.u64 %0, t; }" : "=r"(a) : "l"(p));
    return a;
}

// m16n8k16 fp16 MMA, fp32 accumulate
__device__ __forceinline__ void mma_f16(float* d, const uint4& a, const unsigned* b) {
    asm volatile(
        "mma.sync.aligned.m16n8k16.row.col.f32.f16.f16.f32 "
        "{%0,%1,%2,%3}, {%4,%5,%6,%7}, {%8,%9}, {%0,%1,%2,%3};\n"
        : "+f"(d[0]), "+f"(d[1]), "+f"(d[2]), "+f"(d[3])
        : "r"(a.x), "r"(a.y), "r"(a.z), "r"(a.w), "r"(b[0]), "r"(b[1]));
}

// ---------------- kernel 1: cond head (h + gates) ----------------
__global__ void head_kernel(const float* __restrict__ cond,
                            const float* __restrict__ hW1, const float* __restrict__ hb1,
                            const float* __restrict__ gW1, const float* __restrict__ gb1,
                            const float* __restrict__ gW2, const float* __restrict__ gb2) {
    int b = blockIdx.x;
    int tid = threadIdx.x;
    __shared__ float cs[CONDD];
    __shared__ float ts[24];
    __shared__ float lg[NEXP];

    cs[tid] = cond[b * CONDD + tid];
    __syncthreads();

    if (tid < HD) {
        float acc = hb1[tid];
#pragma unroll 8
        for (int i = 0; i < CONDD; i++) acc += cs[i] * hW1[i * HD + tid];
        g_h[b * HD + tid] = fmaxf(acc, 0.f);
    } else if (tid < HD + 24) {
        int j = tid - HD;
        float acc = gb1[j];
#pragma unroll 8
        for (int i = 0; i < CONDD; i++) acc += cs[i] * gW1[i * 24 + j];
        ts[j] = fmaxf(acc, 0.f);
    }
    __syncthreads();

    if (tid < NEXP) {
        float acc = gb2[tid];
#pragma unroll
        for (int t = 0; t < 24; t++) acc += ts[t] * gW2[t * NEXP + tid];
        lg[tid] = acc;
    }
    __syncthreads();

    if (tid == 0) {
        float mx = lg[0];
#pragma unroll
        for (int e = 1; e < NEXP; e++) mx = fmaxf(mx, lg[e]);
        float ex[NEXP]; float s = 0.f;
#pragma unroll
        for (int e = 0; e < NEXP; e++) { ex[e] = expf(lg[e] - mx); s += ex[e]; }
        float inv = 1.f / s;
#pragma unroll
        for (int e = 0; e < NEXP; e++) g_gw[b * NEXP + e] = ex[e] * inv;
    }
}

// A element (k, m) of the virtual A matrix
__device__ __forceinline__ float aval(int k, int m, const float* __restrict__ x) {
    if (k < 16384) return g_h[m * HD + (k >> 8)] * x[m * INDIM + (k & 255)];
    if (k < 16640) return x[m * INDIM + (k - 16384)];
    if (k < 16704) return g_h[m * HD + (k - 16640)];
    if (k == 16704) return 1.0f;
    return 0.0f;
}

// ---------------- kernel 2: pack A fp16 in fragment order -------------------
// one thread per uint4 fragment: f = ((ktile*4+mtile)*512) + ks*256 + mb*32 + lane
__global__ void packA_kernel(const float* __restrict__ x) {
    int f = blockIdx.x * blockDim.x + threadIdx.x;   // 1,071,104 total
    int lane  = f & 31;
    int mb    = (f >> 5) & 7;
    int ks    = (f >> 8) & 1;
    int mtile = (f >> 9) & 3;
    int ktile = f >> 11;
    int g = lane >> 2, t = lane & 3;
    int m0 = mtile * 128 + mb * 16 + g;
    int kb = ktile * 32 + ks * 16;

    __half2 h0 = __floats2half2_rn(aval(kb + 2*t,     m0,     x), aval(kb + 2*t + 1, m0,     x));
    __half2 h1 = __floats2half2_rn(aval(kb + 2*t,     m0 + 8, x), aval(kb + 2*t + 1, m0 + 8, x));
    __half2 h2 = __floats2half2_rn(aval(kb + 2*t + 8, m0,     x), aval(kb + 2*t + 9, m0,     x));
    __half2 h3 = __floats2half2_rn(aval(kb + 2*t + 8, m0 + 8, x), aval(kb + 2*t + 9, m0 + 8, x));

    uint4 o;
    o.x = *reinterpret_cast<unsigned*>(&h0);
    o.y = *reinterpret_cast<unsigned*>(&h1);
    o.z = *reinterpret_cast<unsigned*>(&h2);
    o.w = *reinterpret_cast<unsigned*>(&h3);
    g_Ah[f] = o;
}

// B element (k, n)
__device__ __forceinline__ float bval(int k, int col, int imul, int ne, int rr, int cl,
                                      const float* __restrict__ hW2, const float* __restrict__ hb2,
                                      const float* __restrict__ base_wp,
                                      const float* __restrict__ base_wn,
                                      const float* __restrict__ base_bn) {
    if (k < 16384)
        return hW2[(size_t)(k >> 8) * TOTALW + col + (size_t)(k & 255) * imul];
    if (k < 16640) {
        int i = k - 16384;
        if (rr == 0)
            return base_wp[(ne * INDIM + i) * DP + cl] + hb2[ne * TPE + i * DP + cl];
        int j = (rr - 1) * 64 + cl;
        return base_wn[(ne * INDIM + i) * DN + j] + hb2[ne * TPE + INDIM * DP + i * DN + j];
    }
    if (k < 16704) {
        if (rr == 0) return 0.f;
        int j = (rr - 1) * 64 + cl;
        return hW2[(size_t)(k - 16640) * TOTALW + ne * TPE + INDIM * (DP + DN) + j];
    }
    if (k == 16704) {
        if (rr == 0) return 0.f;
        int j = (rr - 1) * 64 + cl;
        return base_bn[ne * DN + j] + hb2[ne * TPE + INDIM * (DP + DN) + j];
    }
    return 0.f;
}

// ---------------- kernel 2b: pack B fp16, k-pair layout ---------------------
// one thread per (ktile, n): writes 16 half2 = 4 uint4 contiguous
__global__ void packB_kernel(const float* __restrict__ hW2, const float* __restrict__ hb2,
                             const float* __restrict__ base_wp, const float* __restrict__ base_wn,
                             const float* __restrict__ base_bn) {
    int idx = blockIdx.x * blockDim.x + threadIdx.x;   // 523*1536 = 803,328
    int ktile = idx / NCOL;
    int n = idx - ktile * NCOL;
    int q = n >> 6, cl = n & 63;
    int ne = q / 3, rr = q % 3;
    int col = ne * TPE + (rr == 0 ? cl : INDIM * DP + (rr - 1) * 64 + cl);
    int imul = (rr == 0) ? DP : DN;

    __half2 hv[16];
    if (ktile < 512) {
        // fast path: all 32 k's inside one hW2 row (hh = ktile>>3), stride imul
        const float* src = hW2 + (size_t)(ktile >> 3) * TOTALW + col +
                           (size_t)((ktile & 7) * 32) * imul;
#pragma unroll
        for (int j = 0; j < 16; j++)
            hv[j] = __floats2half2_rn(src[(size_t)(2 * j) * imul],
                                      src[(size_t)(2 * j + 1) * imul]);
    } else {
        int k0 = ktile * 32;
#pragma unroll
        for (int j = 0; j < 16; j++)
            hv[j] = __floats2half2_rn(
                bval(k0 + 2 * j,     col, imul, ne, rr, cl, hW2, hb2, base_wp, base_wn, base_bn),
                bval(k0 + 2 * j + 1, col, imul, ne, rr, cl, hW2, hb2, base_wp, base_wn, base_bn));
    }
    uint4* out = g_Bh + (size_t)idx * 4;
    const uint4* src4 = reinterpret_cast<const uint4*>(hv);
#pragma unroll
    for (int j = 0; j < 4; j++) out[j] = src4[j];
}

// ---------------- kernel 3: 128x128x32 fp16 GEMM, 4-stage cp.async ----------
__global__ void __launch_bounds__(256, 2) gemm_kernel() {
    extern __shared__ char sm[];
    const int tid  = threadIdx.x;
    const int lane = tid & 31, warp = tid >> 5;
    const int g = lane >> 2, t = lane & 3;
    const int mw = (warp >> 2) * 64;     // 2 warps in M
    const int nw = (warp & 3) * 32;      // 4 warps in N
    const int mb0 = (warp >> 2) * 4;

    const int mt   = blockIdx.x & 3;
    const int kspl = blockIdx.x >> 2;
    const int nt   = blockIdx.y;
    const int kt0 = kspl * 87 + (kspl ? 1 : 0);   // 88,87,87,87,87,87
    const int nk  = (kspl == 0) ? 88 : 87;

    const unsigned smb = smem_u32(sm);

    auto load_tile = [&](int ktile, int st) {
        const unsigned ao = smb + (unsigned)(st * SLABB);
        const unsigned bo = ao + ABYTES;
        const uint4* As = g_Ah + ((size_t)ktile * 4 + mt) * 512;
        const uint4* Bs = g_Bh + ((size_t)ktile * NCOL + nt * BN) * 4;
#pragma unroll
        for (int j = 0; j < 2; j++) {
            int c = tid + j * 256;
            cp16(ao + (unsigned)(c * 16), As + c);
            int n = c >> 2, part = c & 3;
            cp16(bo + (unsigned)(n * (BROWW * 4) + part * 16), Bs + c);
        }
    };

#pragma unroll
    for (int s = 0; s < STAGES - 1; s++) {
        load_tile(kt0 + s, s);
        asm volatile("cp.async.commit_group;" ::: "memory");
    }

    float acc[4][4][4];
#pragma unroll
    for (int mi = 0; mi < 4; mi++)
#pragma unroll
        for (int ni = 0; ni < 4; ni++)
#pragma unroll
            for (int e = 0; e < 4; e++) acc[mi][ni][e] = 0.f;

    for (int i = 0; i < nk; i++) {
        asm volatile("cp.async.wait_group %0;" :: "n"(STAGES - 2) : "memory");
        __syncthreads();

        if (i + STAGES - 1 < nk)
            load_tile(kt0 + i + STAGES - 1, (i + STAGES - 1) & (STAGES - 1));
        asm volatile("cp.async.commit_group;" ::: "memory");

        const uint4*    Af = reinterpret_cast<const uint4*>(sm + (i & (STAGES - 1)) * SLABB);
        const unsigned* Bw = reinterpret_cast<const unsigned*>(
                                 sm + (i & (STAGES - 1)) * SLABB + ABYTES);

#pragma unroll
        for (int ks = 0; ks < 2; ks++) {
            uint4 a4[4];
            unsigned bb[4][2];
#pragma unroll
            for (int mi = 0; mi < 4; mi++)
                a4[mi] = Af[ks * 256 + (mb0 + mi) * 32 + lane];
#pragma unroll
            for (int ni = 0; ni < 4; ni++) {
                int n = nw + 8 * ni + g;
                bb[ni][0] = Bw[n * BROWW + ks * 8 + t];
                bb[ni][1] = Bw[n * BROWW + ks * 8 + t + 4];
            }
#pragma unroll
            for (int mi = 0; mi < 4; mi++)
#pragma unroll
                for (int ni = 0; ni < 4; ni++)
                    mma_f16(acc[mi][ni], a4[mi], bb[ni]);
        }
    }

    // write split-K partials
    float* pre = g_pre + (size_t)kspl * (BATCH * NCOL);
    const int rowb = mt * BM + mw;
    const int colb = nt * BN + nw;
#pragma unroll
    for (int mi = 0; mi < 4; mi++) {
#pragma unroll
        for (int ni = 0; ni < 4; ni++) {
            int row = rowb + 16 * mi + g;
            int col = colb + 8 * ni + 2 * t;
            pre[row * NCOL + col]           = acc[mi][ni][0];
            pre[row * NCOL + col + 1]       = acc[mi][ni][1];
            pre[(row + 8) * NCOL + col]     = acc[mi][ni][2];
            pre[(row + 8) * NCOL + col + 1] = acc[mi][ni][3];
        }
    }
}

// ---------------- kernel 4: epilogue (split-K sum, cos/sin/relu, gating) ----
__global__ void epi_kernel(float* __restrict__ out) {
    int b = blockIdx.x;
    int c = threadIdx.x;
    __shared__ float gws[NEXP];
    if (c < NEXP) gws[c] = g_gw[b * NEXP + c];
    __syncthreads();

    const float* p = g_pre + (size_t)b * NCOL;
    const size_t STRIDE = (size_t)BATCH * NCOL;

    if (c < 64) {
        float sc = 0.f, ss = 0.f;
#pragma unroll
        for (int e = 0; e < NEXP; e++) {
            int o = e * 192 + c;
            float v = 0.f;
#pragma unroll
            for (int s = 0; s < NSPLIT; s++) v += p[s * STRIDE + o];
            float sn, co;
            sincosf(v, &sn, &co);
            sc += gws[e] * co;
            ss += gws[e] * sn;
        }
        out[b * 256 + c]      = sc;
        out[b * 256 + 64 + c] = ss;
    } else if (c < 192) {
        int qq = c - 64;
        float snn = 0.f;
#pragma unroll
        for (int e = 0; e < NEXP; e++) {
            int o = e * 192 + 64 + qq;
            float v = 0.f;
#pragma unroll
            for (int s = 0; s < NSPLIT; s++) v += p[s * STRIDE + o];
            snn += gws[e] * fmaxf(v, 0.f);
        }
        out[b * 256 + 128 + qq] = snn;
    }
}

// ---------------- launch ----------------
extern "C" void kernel_launch(void* const* d_in, const int* in_sizes, int n_in,
                              void* d_out, int out_size) {
    const float* x       = (const float*)d_in[0];
    const float* cond    = (const float*)d_in[1];
    const float* base_wp = (const float*)d_in[2];
    const float* base_wn = (const float*)d_in[3];
    const float* base_bn = (const float*)d_in[4];
    const float* hW1     = (const float*)d_in[5];
    const float* hb1     = (const float*)d_in[6];
    const float* hW2     = (const float*)d_in[7];
    const float* hb2     = (const float*)d_in[8];
    const float* gW1     = (const float*)d_in[9];
    const float* gb1     = (const float*)d_in[10];
    const float* gW2     = (const float*)d_in[11];
    const float* gb2     = (const float*)d_in[12];
    float* out = (float*)d_out;

    const int dyn_smem = STAGES * SLABB;   // 73728
    cudaFuncSetAttribute(gemm_kernel, cudaFuncAttributeMaxDynamicSharedMemorySize, dyn_smem);

    head_kernel<<<BATCH, 128>>>(cond, hW1, hb1, gW1, gb1, gW2, gb2);

    packA_kernel<<<(KTILES * 4 * 512) / 256, 256>>>(x);          // 4184 blocks

    packB_kernel<<<(KTILES * NCOL) / 256, 256>>>(hW2, hb2, base_wp, base_wn, base_bn);

    dim3 gg(4 * NSPLIT, NCOL / BN);   // (24, 12) -> 288 CTAs
    gemm_kernel<<<gg, 256, dyn_smem>>>();

    epi_kernel<<<BATCH, 192>>>(out);
}

// round 16
// speedup vs baseline: 2.3579x; 1.0409x over previous
#include <cuda_runtime.h>
#include <cuda_fp16.h>
#include <cstdint>
#include <math.h>

// Problem constants
#define BATCH  512
#define INDIM  256
#define CONDD  128
#define NEXP   8
#define HD     64
#define DP     64
#define DN     128
#define TPE    49280
#define TOTALW 394240
#define NCOL   1536

// K layout: [0,16384) h*x | [16384,16640) x | [16640,16704) h | 16704 ones | pad
#define KP      16736
#define KTILES  523      // KP/32
#define NSPLIT  6

#define BM 128
#define BN 128
#define BK 32
#define STAGES 4
#define ABYTES 8192              // A stage: 512 uint4 fragments
#define BROWW  24                // B smem words per n row (16 used + 8 pad; LDS.64 conflict-free)
#define BBYTES (BM * BROWW * 4)  // 12288
#define SLABB  (ABYTES + BBYTES) // 20480

// ---------------- scratch ----------------
__device__ float g_h[BATCH * HD];
__device__ float g_gw[BATCH * NEXP];
// A fp16, MMA-fragment order: [ktile][mtile 4][ks 2][mblk 8][lane 32] x uint4 (17.1 MB)
__device__ uint4 g_Ah[(size_t)KTILES * 4 * 512];
// B fp16, b-pair-interleaved order: [ktile][n 1536][16 half2 permuted] (51.4 MB)
__device__ uint4 g_Bh[(size_t)KTILES * 1536 * 4];
__device__ float g_pre[(size_t)NSPLIT * BATCH * NCOL];

__device__ __forceinline__ void cp16(unsigned dst, const void* src) {
    asm volatile("cp.async.cg.shared.global [%0], [%1], 16;\n" :: "r"(dst), "l"(src));
}
__device__ __forceinline__ unsigned smem_u32(const void* p) {
    unsigned a;
    asm("{ .reg .u64 t; cvta.to.shared.u64 t, %1; cvt.u32.u64 %0, t; }" : "=r"(a) : "l"(p));
    return a;
}

// m16n8k16 fp16 MMA, fp32 accumulate
__device__ __forceinline__ void mma_f16(float* d, const uint4& a, const uint2& b) {
    asm volatile(
        "mma.sync.aligned.m16n8k16.row.col.f32.f16.f16.f32 "
        "{%0,%1,%2,%3}, {%4,%5,%6,%7}, {%8,%9}, {%0,%1,%2,%3};\n"
        : "+f"(d[0]), "+f"(d[1]), "+f"(d[2]), "+f"(d[3])
        : "r"(a.x), "r"(a.y), "r"(a.z), "r"(a.w), "r"(b.x), "r"(b.y));
}

// ---------------- kernel 1: cond head (h + gates) ----------------
__global__ void head_kernel(const float* __restrict__ cond,
                            const float* __restrict__ hW1, const float* __restrict__ hb1,
                            const float* __restrict__ gW1, const float* __restrict__ gb1,
                            const float* __restrict__ gW2, const float* __restrict__ gb2) {
    int b = blockIdx.x;
    int tid = threadIdx.x;
    __shared__ float cs[CONDD];
    __shared__ float ts[24];
    __shared__ float lg[NEXP];

    cs[tid] = cond[b * CONDD + tid];
    __syncthreads();

    if (tid < HD) {
        float acc = hb1[tid];
#pragma unroll 8
        for (int i = 0; i < CONDD; i++) acc += cs[i] * hW1[i * HD + tid];
        g_h[b * HD + tid] = fmaxf(acc, 0.f);
    } else if (tid < HD + 24) {
        int j = tid - HD;
        float acc = gb1[j];
#pragma unroll 8
        for (int i = 0; i < CONDD; i++) acc += cs[i] * gW1[i * 24 + j];
        ts[j] = fmaxf(acc, 0.f);
    }
    __syncthreads();

    if (tid < NEXP) {
        float acc = gb2[tid];
#pragma unroll
        for (int t = 0; t < 24; t++) acc += ts[t] * gW2[t * NEXP + tid];
        lg[tid] = acc;
    }
    __syncthreads();

    if (tid == 0) {
        float mx = lg[0];
#pragma unroll
        for (int e = 1; e < NEXP; e++) mx = fmaxf(mx, lg[e]);
        float ex[NEXP]; float s = 0.f;
#pragma unroll
        for (int e = 0; e < NEXP; e++) { ex[e] = expf(lg[e] - mx); s += ex[e]; }
        float inv = 1.f / s;
#pragma unroll
        for (int e = 0; e < NEXP; e++) g_gw[b * NEXP + e] = ex[e] * inv;
    }
}

// A element (k, m) of the virtual A matrix
__device__ __forceinline__ float aval(int k, int m, const float* __restrict__ x) {
    if (k < 16384) return g_h[m * HD + (k >> 8)] * x[m * INDIM + (k & 255)];
    if (k < 16640) return x[m * INDIM + (k - 16384)];
    if (k < 16704) return g_h[m * HD + (k - 16640)];
    if (k == 16704) return 1.0f;
    return 0.0f;
}

// ---------------- kernel 2: pack A fp16 in fragment order -------------------
__global__ void packA_kernel(const float* __restrict__ x) {
    int f = blockIdx.x * blockDim.x + threadIdx.x;   // 1,071,104 total
    int lane  = f & 31;
    int mb    = (f >> 5) & 7;
    int ks    = (f >> 8) & 1;
    int mtile = (f >> 9) & 3;
    int ktile = f >> 11;
    int g = lane >> 2, t = lane & 3;
    int m0 = mtile * 128 + mb * 16 + g;
    int kb = ktile * 32 + ks * 16;

    __half2 h0 = __floats2half2_rn(aval(kb + 2*t,     m0,     x), aval(kb + 2*t + 1, m0,     x));
    __half2 h1 = __floats2half2_rn(aval(kb + 2*t,     m0 + 8, x), aval(kb + 2*t + 1, m0 + 8, x));
    __half2 h2 = __floats2half2_rn(aval(kb + 2*t + 8, m0,     x), aval(kb + 2*t + 9, m0,     x));
    __half2 h3 = __floats2half2_rn(aval(kb + 2*t + 8, m0 + 8, x), aval(kb + 2*t + 9, m0 + 8, x));

    uint4 o;
    o.x = *reinterpret_cast<unsigned*>(&h0);
    o.y = *reinterpret_cast<unsigned*>(&h1);
    o.z = *reinterpret_cast<unsigned*>(&h2);
    o.w = *reinterpret_cast<unsigned*>(&h3);
    g_Ah[f] = o;
}

// B element (k, n)
__device__ __forceinline__ float bval(int k, int col, int imul, int ne, int rr, int cl,
                                      const float* __restrict__ hW2, const float* __restrict__ hb2,
                                      const float* __restrict__ base_wp,
                                      const float* __restrict__ base_wn,
                                      const float* __restrict__ base_bn) {
    if (k < 16384)
        return hW2[(size_t)(k >> 8) * TOTALW + col + (size_t)(k & 255) * imul];
    if (k < 16640) {
        int i = k - 16384;
        if (rr == 0)
            return base_wp[(ne * INDIM + i) * DP + cl] + hb2[ne * TPE + i * DP + cl];
        int j = (rr - 1) * 64 + cl;
        return base_wn[(ne * INDIM + i) * DN + j] + hb2[ne * TPE + INDIM * DP + i * DN + j];
    }
    if (k < 16704) {
        if (rr == 0) return 0.f;
        int j = (rr - 1) * 64 + cl;
        return hW2[(size_t)(k - 16640) * TOTALW + ne * TPE + INDIM * (DP + DN) + j];
    }
    if (k == 16704) {
        if (rr == 0) return 0.f;
        int j = (rr - 1) * 64 + cl;
        return base_bn[ne * DN + j] + hb2[ne * TPE + INDIM * (DP + DN) + j];
    }
    return 0.f;
}

// ---------------- kernel 2b: pack B fp16, b-pair-interleaved layout ---------
// word order within a row: w = ks*8 + 2u   holds kpair ks*8 + u      (u=0..3, b0 slot)
//                          w = ks*8 + 2u+1 holds kpair ks*8 + u + 4  (b1 slot)
// -> GEMM thread reads uint2 at word ks*8 + 2t: (b0, b1) in ONE LDS.64.
__global__ void packB_kernel(const float* __restrict__ hW2, const float* __restrict__ hb2,
                             const float* __restrict__ base_wp, const float* __restrict__ base_wn,
                             const float* __restrict__ base_bn) {
    int idx = blockIdx.x * blockDim.x + threadIdx.x;   // 523*1536 = 803,328
    int ktile = idx / NCOL;
    int n = idx - ktile * NCOL;
    int q = n >> 6, cl = n & 63;
    int ne = q / 3, rr = q % 3;
    int col = ne * TPE + (rr == 0 ? cl : INDIM * DP + (rr - 1) * 64 + cl);
    int imul = (rr == 0) ? DP : DN;

    __half2 hv[16];   // kpair order p = 0..15
    if (ktile < 512) {
        const float* src = hW2 + (size_t)(ktile >> 3) * TOTALW + col +
                           (size_t)((ktile & 7) * 32) * imul;
#pragma unroll
        for (int j = 0; j < 16; j++)
            hv[j] = __floats2half2_rn(src[(size_t)(2 * j) * imul],
                                      src[(size_t)(2 * j + 1) * imul]);
    } else {
        int k0 = ktile * 32;
#pragma unroll
        for (int j = 0; j < 16; j++)
            hv[j] = __floats2half2_rn(
                bval(k0 + 2 * j,     col, imul, ne, rr, cl, hW2, hb2, base_wp, base_wn, base_bn),
                bval(k0 + 2 * j + 1, col, imul, ne, rr, cl, hW2, hb2, base_wp, base_wn, base_bn));
    }
    // permute to b-pair-interleaved order
    __half2 pv[16];
#pragma unroll
    for (int ks = 0; ks < 2; ks++)
#pragma unroll
        for (int u = 0; u < 4; u++) {
            pv[ks * 8 + 2 * u]     = hv[ks * 8 + u];
            pv[ks * 8 + 2 * u + 1] = hv[ks * 8 + u + 4];
        }
    uint4* out = g_Bh + (size_t)idx * 4;
    const uint4* src4 = reinterpret_cast<const uint4*>(pv);
#pragma unroll
    for (int j = 0; j < 4; j++) out[j] = src4[j];
}

// ---------------- kernel 3: 128x128x32 fp16 GEMM, 4-stage cp.async ----------
__global__ void __launch_bounds__(256, 2) gemm_kernel() {
    extern __shared__ char sm[];
    const int tid  = threadIdx.x;
    const int lane = tid & 31, warp = tid >> 5;
    const int g = lane >> 2, t = lane & 3;
    const int mw = (warp >> 2) * 64;     // 2 warps in M
    const int nw = (warp & 3) * 32;      // 4 warps in N
    const int mb0 = (warp >> 2) * 4;

    const int mt   = blockIdx.x & 3;
    const int kspl = blockIdx.x >> 2;
    const int nt   = blockIdx.y;
    const int kt0 = kspl * 87 + (kspl ? 1 : 0);   // 88,87,87,87,87,87
    const int nk  = (kspl == 0) ? 88 : 87;

    const unsigned smb = smem_u32(sm);

    auto load_tile = [&](int ktile, int st) {
        const unsigned ao = smb + (unsigned)(st * SLABB);
        const unsigned bo = ao + ABYTES;
        const uint4* As = g_Ah + ((size_t)ktile * 4 + mt) * 512;
        const uint4* Bs = g_Bh + ((size_t)ktile * NCOL + nt * BN) * 4;
#pragma unroll
        for (int j = 0; j < 2; j++) {
            int c = tid + j * 256;
            cp16(ao + (unsigned)(c * 16), As + c);
            int n = c >> 2, part = c & 3;
            cp16(bo + (unsigned)(n * (BROWW * 4) + part * 16), Bs + c);
        }
    };

#pragma unroll
    for (int s = 0; s < STAGES - 1; s++) {
        load_tile(kt0 + s, s);
        asm volatile("cp.async.commit_group;" ::: "memory");
    }

    float acc[4][4][4];
#pragma unroll
    for (int mi = 0; mi < 4; mi++)
#pragma unroll
        for (int ni = 0; ni < 4; ni++)
#pragma unroll
            for (int e = 0; e < 4; e++) acc[mi][ni][e] = 0.f;

    for (int i = 0; i < nk; i++) {
        asm volatile("cp.async.wait_group %0;" :: "n"(STAGES - 2) : "memory");
        __syncthreads();

        if (i + STAGES - 1 < nk)
            load_tile(kt0 + i + STAGES - 1, (i + STAGES - 1) & (STAGES - 1));
        asm volatile("cp.async.commit_group;" ::: "memory");

        const uint4*    Af = reinterpret_cast<const uint4*>(sm + (i & (STAGES - 1)) * SLABB);
        const unsigned* Bw = reinterpret_cast<const unsigned*>(
                                 sm + (i & (STAGES - 1)) * SLABB + ABYTES);

#pragma unroll
        for (int ks = 0; ks < 2; ks++) {
            uint4 a4[4];
            uint2 bb[4];
#pragma unroll
            for (int mi = 0; mi < 4; mi++)
                a4[mi] = Af[ks * 256 + (mb0 + mi) * 32 + lane];
#pragma unroll
            for (int ni = 0; ni < 4; ni++) {
                int n = nw + 8 * ni + g;
                bb[ni] = *reinterpret_cast<const uint2*>(&Bw[n * BROWW + ks * 8 + 2 * t]);
            }
#pragma unroll
            for (int mi = 0; mi < 4; mi++)
#pragma unroll
                for (int ni = 0; ni < 4; ni++)
                    mma_f16(acc[mi][ni], a4[mi], bb[ni]);
        }
    }

    // write split-K partials
    float* pre = g_pre + (size_t)kspl * (BATCH * NCOL);
    const int rowb = mt * BM + mw;
    const int colb = nt * BN + nw;
#pragma unroll
    for (int mi = 0; mi < 4; mi++) {
#pragma unroll
        for (int ni = 0; ni < 4; ni++) {
            int row = rowb + 16 * mi + g;
            int col = colb + 8 * ni + 2 * t;
            pre[row * NCOL + col]           = acc[mi][ni][0];
            pre[row * NCOL + col + 1]       = acc[mi][ni][1];
            pre[(row + 8) * NCOL + col]     = acc[mi][ni][2];
            pre[(row + 8) * NCOL + col + 1] = acc[mi][ni][3];
        }
    }
}

// ---------------- kernel 4: epilogue (split-K sum, cos/sin/relu, gating) ----
__global__ void epi_kernel(float* __restrict__ out) {
    int b = blockIdx.x;
    int c = threadIdx.x;
    __shared__ float gws[NEXP];
    if (c < NEXP) gws[c] = g_gw[b * NEXP + c];
    __syncthreads();

    const float* p = g_pre + (size_t)b * NCOL;
    const size_t STRIDE = (size_t)BATCH * NCOL;

    if (c < 64) {
        float sc = 0.f, ss = 0.f;
#pragma unroll
        for (int e = 0; e < NEXP; e++) {
            int o = e * 192 + c;
            float v = 0.f;
#pragma unroll
            for (int s = 0; s < NSPLIT; s++) v += p[s * STRIDE + o];
            float sn, co;
            sincosf(v, &sn, &co);
            sc += gws[e] * co;
            ss += gws[e] * sn;
        }
        out[b * 256 + c]      = sc;
        out[b * 256 + 64 + c] = ss;
    } else if (c < 192) {
        int qq = c - 64;
        float snn = 0.f;
#pragma unroll
        for (int e = 0; e < NEXP; e++) {
            int o = e * 192 + 64 + qq;
            float v = 0.f;
#pragma unroll
            for (int s = 0; s < NSPLIT; s++) v += p[s * STRIDE + o];
            snn += gws[e] * fmaxf(v, 0.f);
        }
        out[b * 256 + 128 + qq] = snn;
    }
}

// ---------------- launch ----------------
extern "C" void kernel_launch(void* const* d_in, const int* in_sizes, int n_in,
                              void* d_out, int out_size) {
    const float* x       = (const float*)d_in[0];
    const float* cond    = (const float*)d_in[1];
    const float* base_wp = (const float*)d_in[2];
    const float* base_wn = (const float*)d_in[3];
    const float* base_bn = (const float*)d_in[4];
    const float* hW1     = (const float*)d_in[5];
    const float* hb1     = (const float*)d_in[6];
    const float* hW2     = (const float*)d_in[7];
    const float* hb2     = (const float*)d_in[8];
    const float* gW1     = (const float*)d_in[9];
    const float* gb1     = (const float*)d_in[10];
    const float* gW2     = (const float*)d_in[11];
    const float* gb2     = (const float*)d_in[12];
    float* out = (float*)d_out;

    const int dyn_smem = STAGES * SLABB;   // 81920
    cudaFuncSetAttribute(gemm_kernel, cudaFuncAttributeMaxDynamicSharedMemorySize, dyn_smem);

    head_kernel<<<BATCH, 128>>>(cond, hW1, hb1, gW1, gb1, gW2, gb2);

    packA_kernel<<<(KTILES * 4 * 512) / 256, 256>>>(x);

    packB_kernel<<<(KTILES * NCOL) / 256, 256>>>(hW2, hb2, base_wp, base_wn, base_bn);

    dim3 gg(4 * NSPLIT, NCOL / BN);   // (24, 12) -> 288 CTAs
    gemm_kernel<<<gg, 256, dyn_smem>>>();

    epi_kernel<<<BATCH, 192>>>(out);
}

// round 17
// speedup vs baseline: 2.4539x; 1.0407x over previous
#include <cuda_runtime.h>
#include <cuda_fp16.h>
#include <cstdint>
#include <math.h>

// Problem constants
#define BATCH  512
#define INDIM  256
#define CONDD  128
#define NEXP   8
#define HD     64
#define DP     64
#define DN     128
#define TPE    49280
#define TOTALW 394240
#define NCOL   1536

// K layout: [0,16384) h*x | [16384,16640) x | [16640,16704) h | 16704 ones | pad
#define KP      16736
#define KTILES  523      // real k32 tiles
#define KTP     524      // padded to even (pair mainloop)
#define NPAIRS  262
#define NSPLIT  6

#define BM 128
#define BN 128
#define ABYTES 8192              // A per ktile: 512 uint4 fragments
#define BBYTES 8192              // B per ktile: 128 n-rows x 16 words (64B), no pad
#define SUBB   (ABYTES + BBYTES) // 16384 per ktile
#define PAIRB  (2 * SUBB)        // 32768 per pair
#define PSTAGES 3                // pair stages -> 98304 B smem

// ---------------- scratch ----------------
__device__ float g_h[BATCH * HD];
__device__ float g_gw[BATCH * NEXP];
// A fp16, MMA-fragment order: [ktile][mtile 4][ks 2][mblk 8][lane 32] x uint4
__device__ uint4 g_Ah[(size_t)KTP * 4 * 512];
// B fp16: [ktile][n 1536][16 half2], word 4u+j <- kpair u + 4j (u,j in 0..3)
__device__ uint4 g_Bh[(size_t)KTP * 1536 * 4];
__device__ float g_pre[(size_t)NSPLIT * BATCH * NCOL];

__device__ __forceinline__ void cp16(unsigned dst, const void* src) {
    asm volatile("cp.async.cg.shared.global [%0], [%1], 16;\n" :: "r"(dst), "l"(src));
}
__device__ __forceinline__ unsigned smem_u32(const void* p) {
    unsigned a;
    asm("{ .reg .u64 t; cvta.to.shared.u64 t, %1; cvt.u32.u64 %0, t; }" : "=r"(a) : "l"(p));
    return a;
}

// m16n8k16 fp16 MMA, fp32 accumulate
__device__ __forceinline__ void mma_f16(float* d, const uint4& a, unsigned b0, unsigned b1) {
    asm volatile(
        "mma.sync.aligned.m16n8k16.row.col.f32.f16.f16.f32 "
        "{%0,%1,%2,%3}, {%4,%5,%6,%7}, {%8,%9}, {%0,%1,%2,%3};\n"
        : "+f"(d[0]), "+f"(d[1]), "+f"(d[2]), "+f"(d[3])
        : "r"(a.x), "r"(a.y), "r"(a.z), "r"(a.w), "r"(b0), "r"(b1));
}

// ---------------- kernel 1: cond head (h + gates) ----------------
__global__ void head_kernel(const float* __restrict__ cond,
                            const float* __restrict__ hW1, const float* __restrict__ hb1,
                            const float* __restrict__ gW1, const float* __restrict__ gb1,
                            const float* __restrict__ gW2, const float* __restrict__ gb2) {
    int b = blockIdx.x;
    int tid = threadIdx.x;
    __shared__ float cs[CONDD];
    __shared__ float ts[24];
    __shared__ float lg[NEXP];

    cs[tid] = cond[b * CONDD + tid];
    __syncthreads();

    if (tid < HD) {
        float acc = hb1[tid];
#pragma unroll 8
        for (int i = 0; i < CONDD; i++) acc += cs[i] * hW1[i * HD + tid];
        g_h[b * HD + tid] = fmaxf(acc, 0.f);
    } else if (tid < HD + 24) {
        int j = tid - HD;
        float acc = gb1[j];
#pragma unroll 8
        for (int i = 0; i < CONDD; i++) acc += cs[i] * gW1[i * 24 + j];
        ts[j] = fmaxf(acc, 0.f);
    }
    __syncthreads();

    if (tid < NEXP) {
        float acc = gb2[tid];
#pragma unroll
        for (int t = 0; t < 24; t++) acc += ts[t] * gW2[t * NEXP + tid];
        lg[tid] = acc;
    }
    __syncthreads();

    if (tid == 0) {
        float mx = lg[0];
#pragma unroll
        for (int e = 1; e < NEXP; e++) mx = fmaxf(mx, lg[e]);
        float ex[NEXP]; float s = 0.f;
#pragma unroll
        for (int e = 0; e < NEXP; e++) { ex[e] = expf(lg[e] - mx); s += ex[e]; }
        float inv = 1.f / s;
#pragma unroll
        for (int e = 0; e < NEXP; e++) g_gw[b * NEXP + e] = ex[e] * inv;
    }
}

// A element (k, m) of the virtual A matrix (0 for k >= 16705, incl. pad to 16768)
__device__ __forceinline__ float aval(int k, int m, const float* __restrict__ x) {
    if (k < 16384) return g_h[m * HD + (k >> 8)] * x[m * INDIM + (k & 255)];
    if (k < 16640) return x[m * INDIM + (k - 16384)];
    if (k < 16704) return g_h[m * HD + (k - 16640)];
    if (k == 16704) return 1.0f;
    return 0.0f;
}

// ---------------- kernel 2: pack A fp16 in fragment order -------------------
__global__ void packA_kernel(const float* __restrict__ x) {
    int f = blockIdx.x * blockDim.x + threadIdx.x;   // KTP*4*512 total
    int lane  = f & 31;
    int mb    = (f >> 5) & 7;
    int ks    = (f >> 8) & 1;
    int mtile = (f >> 9) & 3;
    int ktile = f >> 11;
    int g = lane >> 2, t = lane & 3;
    int m0 = mtile * 128 + mb * 16 + g;
    int kb = ktile * 32 + ks * 16;

    __half2 h0 = __floats2half2_rn(aval(kb + 2*t,     m0,     x), aval(kb + 2*t + 1, m0,     x));
    __half2 h1 = __floats2half2_rn(aval(kb + 2*t,     m0 + 8, x), aval(kb + 2*t + 1, m0 + 8, x));
    __half2 h2 = __floats2half2_rn(aval(kb + 2*t + 8, m0,     x), aval(kb + 2*t + 9, m0,     x));
    __half2 h3 = __floats2half2_rn(aval(kb + 2*t + 8, m0 + 8, x), aval(kb + 2*t + 9, m0 + 8, x));

    uint4 o;
    o.x = *reinterpret_cast<unsigned*>(&h0);
    o.y = *reinterpret_cast<unsigned*>(&h1);
    o.z = *reinterpret_cast<unsigned*>(&h2);
    o.w = *reinterpret_cast<unsigned*>(&h3);
    g_Ah[f] = o;
}

// B element (k, n); 0 for pad k
__device__ __forceinline__ float bval(int k, int col, int imul, int ne, int rr, int cl,
                                      const float* __restrict__ hW2, const float* __restrict__ hb2,
                                      const float* __restrict__ base_wp,
                                      const float* __restrict__ base_wn,
                                      const float* __restrict__ base_bn) {
    if (k < 16384)
        return hW2[(size_t)(k >> 8) * TOTALW + col + (size_t)(k & 255) * imul];
    if (k < 16640) {
        int i = k - 16384;
        if (rr == 0)
            return base_wp[(ne * INDIM + i) * DP + cl] + hb2[ne * TPE + i * DP + cl];
        int j = (rr - 1) * 64 + cl;
        return base_wn[(ne * INDIM + i) * DN + j] + hb2[ne * TPE + INDIM * DP + i * DN + j];
    }
    if (k < 16704) {
        if (rr == 0) return 0.f;
        int j = (rr - 1) * 64 + cl;
        return hW2[(size_t)(k - 16640) * TOTALW + ne * TPE + INDIM * (DP + DN) + j];
    }
    if (k == 16704) {
        if (rr == 0) return 0.f;
        int j = (rr - 1) * 64 + cl;
        return base_bn[ne * DN + j] + hb2[ne * TPE + INDIM * (DP + DN) + j];
    }
    return 0.f;
}

// ---------------- kernel 2b: pack B fp16, quad-interleaved layout -----------
// word w = 4u + j holds kpair u + 4j  (u = t, j = frag slot)
// -> GEMM thread reads ONE uint4 at word 4t: {ks0.b0, ks0.b1, ks1.b0, ks1.b1}
__global__ void packB_kernel(const float* __restrict__ hW2, const float* __restrict__ hb2,
                             const float* __restrict__ base_wp, const float* __restrict__ base_wn,
                             const float* __restrict__ base_bn) {
    int idx = blockIdx.x * blockDim.x + threadIdx.x;   // KTP*1536
    int ktile = idx / NCOL;
    int n = idx - ktile * NCOL;
    int q = n >> 6, cl = n & 63;
    int ne = q / 3, rr = q % 3;
    int col = ne * TPE + (rr == 0 ? cl : INDIM * DP + (rr - 1) * 64 + cl);
    int imul = (rr == 0) ? DP : DN;

    __half2 hv[16];   // kpair order p = 0..15
    if (ktile < 512) {
        const float* src = hW2 + (size_t)(ktile >> 3) * TOTALW + col +
                           (size_t)((ktile & 7) * 32) * imul;
#pragma unroll
        for (int j = 0; j < 16; j++)
            hv[j] = __floats2half2_rn(src[(size_t)(2 * j) * imul],
                                      src[(size_t)(2 * j + 1) * imul]);
    } else {
        int k0 = ktile * 32;
#pragma unroll
        for (int j = 0; j < 16; j++)
            hv[j] = __floats2half2_rn(
                bval(k0 + 2 * j,     col, imul, ne, rr, cl, hW2, hb2, base_wp, base_wn, base_bn),
                bval(k0 + 2 * j + 1, col, imul, ne, rr, cl, hW2, hb2, base_wp, base_wn, base_bn));
    }
    // quad-interleave
    __half2 pv[16];
#pragma unroll
    for (int u = 0; u < 4; u++) {
        pv[4 * u + 0] = hv[u];
        pv[4 * u + 1] = hv[u + 4];
        pv[4 * u + 2] = hv[u + 8];
        pv[4 * u + 3] = hv[u + 12];
    }
    uint4* out = g_Bh + (size_t)idx * 4;
    const uint4* src4 = reinterpret_cast<const uint4*>(pv);
#pragma unroll
    for (int j = 0; j < 4; j++) out[j] = src4[j];
}

// ---------------- kernel 3: 128x128x64 fp16 GEMM, 3 pair-stages -------------
__global__ void __launch_bounds__(256, 2) gemm_kernel() {
    extern __shared__ char sm[];
    const int tid  = threadIdx.x;
    const int lane = tid & 31, warp = tid >> 5;
    const int g = lane >> 2, t = lane & 3;
    const int mw = (warp >> 2) * 64;     // 2 warps in M
    const int nw = (warp & 3) * 32;      // 4 warps in N
    const int mb0 = (warp >> 2) * 4;

    const int mt   = blockIdx.x & 3;
    const int kspl = blockIdx.x >> 2;
    const int nt   = blockIdx.y;
    const int p0 = kspl * 43 + (kspl < 4 ? kspl : 4);   // pair sections: 44,44,44,44,43,43
    const int np = (kspl < 4) ? 44 : 43;

    const unsigned smb = smem_u32(sm);

    auto load_pair = [&](int pr, int st) {
        const unsigned so = smb + (unsigned)(st * PAIRB);
#pragma unroll
        for (int sub = 0; sub < 2; sub++) {
            const int ktile = 2 * pr + sub;
            const unsigned ao = so + (unsigned)(sub * SUBB);
            const unsigned bo = ao + ABYTES;
            const uint4* As = g_Ah + ((size_t)ktile * 4 + mt) * 512;
            const uint4* Bs = g_Bh + ((size_t)ktile * NCOL + nt * BN) * 4;
#pragma unroll
            for (int j = 0; j < 2; j++) {
                int c = tid + j * 256;
                cp16(ao + (unsigned)(c * 16), As + c);
                int n = c >> 2, part = c & 3;
                cp16(bo + (unsigned)(n * 64 + part * 16), Bs + c);
            }
        }
    };

    load_pair(p0, 0);
    asm volatile("cp.async.commit_group;" ::: "memory");
    load_pair(p0 + 1, 1);
    asm volatile("cp.async.commit_group;" ::: "memory");

    float acc[4][4][4];
#pragma unroll
    for (int mi = 0; mi < 4; mi++)
#pragma unroll
        for (int ni = 0; ni < 4; ni++)
#pragma unroll
            for (int e = 0; e < 4; e++) acc[mi][ni][e] = 0.f;

    for (int i = 0; i < np; i++) {
        if (i + 1 < np) asm volatile("cp.async.wait_group 1;" ::: "memory");
        else            asm volatile("cp.async.wait_group 0;" ::: "memory");
        __syncthreads();   // stage i landed; all warps done with stage (i-1) buffer

        if (i + 2 < np) load_pair(p0 + i + 2, (i + 2) % PSTAGES);
        asm volatile("cp.async.commit_group;" ::: "memory");

        const char* stage = sm + (i % PSTAGES) * PAIRB;
#pragma unroll
        for (int sub = 0; sub < 2; sub++) {
            const uint4* Af = reinterpret_cast<const uint4*>(stage + sub * SUBB);
            const uint4* B4 = reinterpret_cast<const uint4*>(stage + sub * SUBB + ABYTES);

            uint4 bq[4];
#pragma unroll
            for (int ni = 0; ni < 4; ni++) {
                int n = nw + 8 * ni + g;
                bq[ni] = B4[n * 4 + t];   // LDS.128: both ks fragments
            }
#pragma unroll
            for (int ks = 0; ks < 2; ks++) {
                uint4 a4[4];
#pragma unroll
                for (int mi = 0; mi < 4; mi++)
                    a4[mi] = Af[ks * 256 + (mb0 + mi) * 32 + lane];
#pragma unroll
                for (int mi = 0; mi < 4; mi++)
#pragma unroll
                    for (int ni = 0; ni < 4; ni++) {
                        if (ks == 0) mma_f16(acc[mi][ni], a4[mi], bq[ni].x, bq[ni].y);
                        else         mma_f16(acc[mi][ni], a4[mi], bq[ni].z, bq[ni].w);
                    }
            }
        }
    }

    // write split-K partials
    float* pre = g_pre + (size_t)kspl * (BATCH * NCOL);
    const int rowb = mt * BM + mw;
    const int colb = nt * BN + nw;
#pragma unroll
    for (int mi = 0; mi < 4; mi++) {
#pragma unroll
        for (int ni = 0; ni < 4; ni++) {
            int row = rowb + 16 * mi + g;
            int col = colb + 8 * ni + 2 * t;
            pre[row * NCOL + col]           = acc[mi][ni][0];
            pre[row * NCOL + col + 1]       = acc[mi][ni][1];
            pre[(row + 8) * NCOL + col]     = acc[mi][ni][2];
            pre[(row + 8) * NCOL + col + 1] = acc[mi][ni][3];
        }
    }
}

// ---------------- kernel 4: epilogue (split-K sum, cos/sin/relu, gating) ----
__global__ void epi_kernel(float* __restrict__ out) {
    int b = blockIdx.x;
    int c = threadIdx.x;
    __shared__ float gws[NEXP];
    if (c < NEXP) gws[c] = g_gw[b * NEXP + c];
    __syncthreads();

    const float* p = g_pre + (size_t)b * NCOL;
    const size_t STRIDE = (size_t)BATCH * NCOL;

    if (c < 64) {
        float sc = 0.f, ss = 0.f;
#pragma unroll
        for (int e = 0; e < NEXP; e++) {
            int o = e * 192 + c;
            float v = 0.f;
#pragma unroll
            for (int s = 0; s < NSPLIT; s++) v += p[s * STRIDE + o];
            float sn, co;
            sincosf(v, &sn, &co);
            sc += gws[e] * co;
            ss += gws[e] * sn;
        }
        out[b * 256 + c]      = sc;
        out[b * 256 + 64 + c] = ss;
    } else if (c < 192) {
        int qq = c - 64;
        float snn = 0.f;
#pragma unroll
        for (int e = 0; e < NEXP; e++) {
            int o = e * 192 + 64 + qq;
            float v = 0.f;
#pragma unroll
            for (int s = 0; s < NSPLIT; s++) v += p[s * STRIDE + o];
            snn += gws[e] * fmaxf(v, 0.f);
        }
        out[b * 256 + 128 + qq] = snn;
    }
}

// ---------------- launch ----------------
extern "C" void kernel_launch(void* const* d_in, const int* in_sizes, int n_in,
                              void* d_out, int out_size) {
    const float* x       = (const float*)d_in[0];
    const float* cond    = (const float*)d_in[1];
    const float* base_wp = (const float*)d_in[2];
    const float* base_wn = (const float*)d_in[3];
    const float* base_bn = (const float*)d_in[4];
    const float* hW1     = (const float*)d_in[5];
    const float* hb1     = (const float*)d_in[6];
    const float* hW2     = (const float*)d_in[7];
    const float* hb2     = (const float*)d_in[8];
    const float* gW1     = (const float*)d_in[9];
    const float* gb1     = (const float*)d_in[10];
    const float* gW2     = (const float*)d_in[11];
    const float* gb2     = (const float*)d_in[12];
    float* out = (float*)d_out;

    const int dyn_smem = PSTAGES * PAIRB;   // 98304
    cudaFuncSetAttribute(gemm_kernel, cudaFuncAttributeMaxDynamicSharedMemorySize, dyn_smem);

    head_kernel<<<BATCH, 128>>>(cond, hW1, hb1, gW1, gb1, gW2, gb2);

    packA_kernel<<<(KTP * 4 * 512) / 256, 256>>>(x);

    packB_kernel<<<(KTP * NCOL) / 256, 256>>>(hW2, hb2, base_wp, base_wn, base_bn);

    dim3 gg(4 * NSPLIT, NCOL / BN);   // (24, 12) -> 288 CTAs
    gemm_kernel<<<gg, 256, dyn_smem>>>();

    epi_kernel<<<BATCH, 192>>>(out);
}